// round 12
// baseline (speedup 1.0000x reference)
#include <cuda_runtime.h>
#include <cstdint>
#include <math.h>

// ---------------------------------------------------------------------------
// Scratch: states + transposed pair-splatted weights + x-gates blobs.
// ---------------------------------------------------------------------------
#define ST0 2097152ull   // 8*64*64*64
#define ST1 1048576ull   // 8*128*32*32
#define WT0_SZ (2ull * 72 * 64 * 64)
#define WT1_SZ (2ull * 72 * 128 * 128)

#define OFF_HF0A 0ull
#define OFF_HF0B (OFF_HF0A + ST0)
#define OFF_CF0  (OFF_HF0B + ST0)
#define OFF_HB0A (OFF_CF0  + ST0)
#define OFF_HB0B (OFF_HB0A + ST0)
#define OFF_CB0  (OFF_HB0B + ST0)
#define OFF_HF1A (OFF_CB0  + ST0)
#define OFF_HF1B (OFF_HF1A + ST1)
#define OFF_CF1  (OFF_HF1B + ST1)
#define OFF_HB1A (OFF_CF1  + ST1)
#define OFF_HB1B (OFF_HB1A + ST1)
#define OFF_CB1  (OFF_HB1B + ST1)
#define OFF_WTF0 (OFF_CB1  + ST1)
#define OFF_WTB0 (OFF_WTF0 + WT0_SZ)
#define OFF_WTF1 (OFF_WTB0 + WT0_SZ)
#define OFF_WTB1 (OFF_WTF1 + WT1_SZ)
#define BUF_TOTAL (OFF_WTB1 + WT1_SZ)

__device__ float g_buf[BUF_TOTAL];
#define STATE_TOTAL (OFF_WTF0)

#define XG0_CELL 67108864ull
#define XG1_CELL 33554432ull
#define XG_F0 0ull
#define XG_B0 (XG_F0 + XG0_CELL)
#define XG_F1 (XG_B0 + XG0_CELL)
#define XG_B1 (XG_F1 + XG1_CELL)
#define XG_TOTAL (XG_B1 + XG1_CELL)

__device__ unsigned long long g_xg[XG_TOTAL];

__global__ void zero_kernel(float* __restrict__ p, size_t n) {
    size_t i = (size_t)blockIdx.x * blockDim.x + threadIdx.x;
    if (i < n) p[i] = 0.0f;
}

// ---------------------------------------------------------------------------
// ONE merged weight transpose for all 4 cells (keeps prelude to 2 launches so
// ncu -s 5 lands on a real conv kernel).
// ---------------------------------------------------------------------------
__global__ void transpose_all(const float* __restrict__ W0f, const float* __restrict__ W0b,
                              const float* __restrict__ W1f, const float* __restrict__ W1b,
                              float* __restrict__ o0f, float* __restrict__ o0b,
                              float* __restrict__ o1f, float* __restrict__ o1b)
{
    const int t0 = 294912, t1 = 1179648;
    int j = blockIdx.x * 256 + threadIdx.x;
    const float* W; float* O; int C;
    if (j < t0)              { W = W0f; O = o0f; C = 64; }
    else if ((j -= t0) < t0) { W = W0b; O = o0b; C = 64; }
    else if ((j -= t0) < t1) { W = W1f; O = o1f; C = 128; }
    else if ((j -= t1) < t1) { W = W1b; O = o1b; C = 128; }
    else return;
    int tap = j % 9;
    int r = j / 9;
    int o = r % 64; r /= 64;
    int ci = r % (2 * C);
    int g = r / (2 * C);
    int row = (o >> 4) * C + g * 16 + (o & 15);
    float w = W[((size_t)row * (2 * C) + ci) * 9 + tap];
    reinterpret_cast<float2*>(O)[j] = make_float2(w, w);
}

// ---------------------------------------------------------------------------
// helpers
// ---------------------------------------------------------------------------
__device__ __forceinline__ void cpa16(unsigned int dst, const float* src) {
    asm volatile("cp.async.cg.shared.global [%0], [%1], 16;" :: "r"(dst), "l"(src));
}
__device__ __forceinline__ void cpa16z(unsigned int dst, const float* src, bool v) {
    int sz = v ? 16 : 0;
    asm volatile("cp.async.cg.shared.global [%0], [%1], 16, %2;"
                 :: "r"(dst), "l"(src), "r"(sz));
}
__device__ __forceinline__ void cpa_commit() {
    asm volatile("cp.async.commit_group;" ::: "memory");
}
__device__ __forceinline__ unsigned long long pack2(float lo, float hi) {
    unsigned long long r;
    asm("mov.b64 %0, {%1, %2};" : "=l"(r) : "f"(lo), "f"(hi));
    return r;
}
__device__ __forceinline__ void fma2(unsigned long long& d,
                                     unsigned long long a, unsigned long long b) {
    asm("fma.rn.f32x2 %0, %1, %2, %0;" : "+l"(d) : "l"(a), "l"(b));
}
__device__ __forceinline__ void unpack2(unsigned long long v, float& lo, float& hi) {
    asm("mov.b64 {%0, %1}, %2;" : "=f"(lo), "=f"(hi) : "l"(v));
}

#define TSP 16
#define CI_BLK 8
// input row: 28 floats covering global cols [tileX-4, tileX+23]; chunks 0..5 used
#define SIN_ROW 28
#define SIN_CI (18 * SIN_ROW)              // 504 floats per ci
#define SIN_BUF (CI_BLK * SIN_CI)          // 4032 floats per buffer
#define SW_BUF (CI_BLK * 1152)             // 9216 floats per buffer
#define SMEM_BYTES ((2 * SIN_BUF + 2 * SW_BUF) * 4)   // 105984 B

// ---------------------------------------------------------------------------
// Shared conv core: accumulates 64 outputs x 256 pixels over nCi channels of
// `base` using weight rows starting at wbase. acc2 in caller registers.
// ---------------------------------------------------------------------------
template<int H, int W>
__device__ __forceinline__ void conv_core(
    const float* __restrict__ base, const float* __restrict__ wbase,
    int nCi, int tileY, int tileX, int tid, int ty, int rp, int cq,
    float* sInF, float* sWF, unsigned int sInAddr, unsigned int sWAddr,
    unsigned long long (&acc2)[8][2][2])
{
    const int NBLK = nCi / CI_BLK;

    auto stage = [&](int ci0s, int dbuf) {
        // inputs: CI_BLK x 18 rows x 6 chunks of 16B
        for (int i = tid; i < CI_BLK * 108; i += 256) {
            const int ciL = i / 108;
            const int rem = i - ciL * 108;
            const int r = rem / 6, k = rem - r * 6;
            const float* srcp = base + (size_t)(ci0s + ciL) * H * W;
            const int gy = tileY - 1 + r;
            const bool vrow = (gy >= 0 && gy < H);
            const bool vcol = (k == 0) ? (tileX > 0)
                            : ((k < 5) ? true : (tileX + 16 < W));
            const bool v = vrow && vcol;
            const float* sp = srcp + (v ? (gy * W + tileX - 4 + 4 * k) : 0);
            cpa16z(sInAddr + (unsigned int)((((dbuf * CI_BLK + ciL) * SIN_CI)
                                             + r * SIN_ROW + 4 * k) * 4), sp, v);
        }
        // weights: CI_BLK*1152 contiguous floats (pairs), 16B chunks
        const float* wsrc = wbase + (size_t)ci0s * 1152;
        for (int i = tid; i < (CI_BLK * 1152) / 4; i += 256) {
            cpa16(sWAddr + (unsigned int)((dbuf * SW_BUF + i * 4) * 4), wsrc + i * 4);
        }
        cpa_commit();
    };

    stage(0, 0);
    for (int blk = 0; blk < NBLK; ++blk) {
        const int cur = blk & 1;
        if (blk + 1 < NBLK) {
            stage((blk + 1) * CI_BLK, cur ^ 1);
            asm volatile("cp.async.wait_group 1;" ::: "memory");
        } else {
            asm volatile("cp.async.wait_group 0;" ::: "memory");
        }
        __syncthreads();

        #pragma unroll 4
        for (int ciL = 0; ciL < CI_BLK; ciL++) {
            unsigned long long xp[4][5];
            const float* sci = sInF + (cur * CI_BLK + ciL) * SIN_CI;
            #pragma unroll
            for (int i = 0; i < 4; i++) {
                float xs[6];
                #pragma unroll
                for (int j = 0; j < 6; j++)
                    xs[j] = sci[(2 * rp + i) * SIN_ROW + 3 + 4 * cq + j];
                #pragma unroll
                for (int j = 0; j < 5; j++)
                    xp[i][j] = pack2(xs[j], xs[j + 1]);
            }
            const unsigned long long* wci = reinterpret_cast<const unsigned long long*>(
                sWF + (cur * SW_BUF + ciL * 1152));
            #pragma unroll
            for (int tap = 0; tap < 9; tap++) {
                const int ky = tap / 3, kx = tap % 3;
                #pragma unroll
                for (int k = 0; k < 8; k++) {
                    const unsigned long long w2 = wci[(k * 8 + ty) * 9 + tap];
                    fma2(acc2[k][0][0], xp[ky][kx],     w2);
                    fma2(acc2[k][0][1], xp[ky][kx + 2], w2);
                    fma2(acc2[k][1][0], xp[ky + 1][kx],     w2);
                    fma2(acc2[k][1][1], xp[ky + 1][kx + 2], w2);
                }
            }
        }
        __syncthreads();
    }
}

// ---------------------------------------------------------------------------
// Precompute: xgates = W_x (x) x for ALL (t,b). grid (tiles, C/16, T*B).
// ---------------------------------------------------------------------------
template<int C, int H, int W>
__global__ __launch_bounds__(256, 2)
void conv_x_pre(const float* __restrict__ feat,
                const float* __restrict__ WT2,
                unsigned long long* __restrict__ xg,
                const int* __restrict__ mask)
{
    const int z = blockIdx.z;
    if (mask[z] <= 0) return;
    const int coGrp = blockIdx.y;
    const int tilesX = W / TSP;
    const int nTiles = (H / TSP) * tilesX;
    const int tileY  = (blockIdx.x / tilesX) * TSP;
    const int tileX  = (blockIdx.x % tilesX) * TSP;
    const int tid  = threadIdx.x;
    const int ty   = tid >> 5;
    const int lane = tid & 31;
    const int rp   = lane >> 2;
    const int cq   = lane & 3;

    extern __shared__ float dsm[];
    float* sInF = dsm;
    float* sWF  = dsm + 2 * SIN_BUF;
    const unsigned int sInAddr = (unsigned int)__cvta_generic_to_shared(sInF);
    const unsigned int sWAddr  = (unsigned int)__cvta_generic_to_shared(sWF);

    unsigned long long acc2[8][2][2];
    #pragma unroll
    for (int k = 0; k < 8; k++)
        #pragma unroll
        for (int r = 0; r < 2; r++)
            #pragma unroll
            for (int cc = 0; cc < 2; cc++)
                acc2[k][r][cc] = 0ull;

    conv_core<H, W>(feat + (size_t)z * C * H * W,
                    WT2 + (size_t)(coGrp * 2 * C) * 1152,     // x-part rows
                    C, tileY, tileX, tid, ty, rp, cq,
                    sInF, sWF, sInAddr, sWAddr, acc2);

    unsigned long long* blob = xg +
        (((size_t)z * (C / 16) + coGrp) * nTiles + blockIdx.x) * 8192;
    #pragma unroll
    for (int k = 0; k < 8; k++)
        #pragma unroll
        for (int r = 0; r < 2; r++)
            #pragma unroll
            for (int cp = 0; cp < 2; cp++)
                blob[((((k * 2 + r) * 2 + cp) << 8) + tid)] = acc2[k][r][cp];
}

// ---------------------------------------------------------------------------
// Recurrent: h-part conv + xgate + bias + LSTM update.
// ---------------------------------------------------------------------------
template<int C, int H, int W>
__global__ __launch_bounds__(256, 2)
void convlstm_step(const float* __restrict__ h_in,
                   float* __restrict__ h_out,
                   float* __restrict__ c,
                   const float* __restrict__ WT2, const float* __restrict__ bias,
                   const unsigned long long* __restrict__ xg,
                   const int* __restrict__ mask_t, int t)
{
    const int b = blockIdx.z;
    const int coGrp = blockIdx.y;
    const int coBase = coGrp * 16;
    const int tilesX = W / TSP;
    const int nTiles = (H / TSP) * tilesX;
    const int tileY  = (blockIdx.x / tilesX) * TSP;
    const int tileX  = (blockIdx.x % tilesX) * TSP;
    const int tid  = threadIdx.x;

    if (mask_t[b] <= 0) {
        for (int i = tid; i < 16 * TSP * TSP; i += 256) {
            const int chL = i >> 8;
            const int rem = i & 255;
            const int y = tileY + (rem >> 4);
            const int xx = tileX + (rem & 15);
            const size_t idx = ((size_t)b * C + coBase + chL) * (size_t)(H * W)
                             + (size_t)y * W + xx;
            h_out[idx] = h_in[idx];
        }
        return;
    }

    const int ty   = tid >> 5;
    const int lane = tid & 31;
    const int rp   = lane >> 2;
    const int cq   = lane & 3;

    extern __shared__ float dsm[];
    float* sInF = dsm;
    float* sWF  = dsm + 2 * SIN_BUF;
    const unsigned int sInAddr = (unsigned int)__cvta_generic_to_shared(sInF);
    const unsigned int sWAddr  = (unsigned int)__cvta_generic_to_shared(sWF);

    unsigned long long acc2[8][2][2];
    #pragma unroll
    for (int k = 0; k < 8; k++)
        #pragma unroll
        for (int r = 0; r < 2; r++)
            #pragma unroll
            for (int cc = 0; cc < 2; cc++)
                acc2[k][r][cc] = 0ull;

    conv_core<H, W>(h_in + (size_t)b * C * H * W,
                    WT2 + (size_t)(coGrp * 2 * C + C) * 1152,  // h-part rows
                    C, tileY, tileX, tid, ty, rp, cq,
                    sInF, sWF, sInAddr, sWAddr, acc2);

    const int z = t * 8 + b;
    const unsigned long long* blob = xg +
        (((size_t)z * (C / 16) + coGrp) * nTiles + blockIdx.x) * 8192;

    #pragma unroll
    for (int j = 0; j < 2; j++) {
        const int ch = coBase + j * 8 + ty;
        const float bi = bias[0 * C + ch];
        const float bf = bias[1 * C + ch];
        const float bo = bias[2 * C + ch];
        const float bg = bias[3 * C + ch];
        #pragma unroll
        for (int r = 0; r < 2; r++) {
            const int y = tileY + 2 * rp + r;
            #pragma unroll
            for (int cp = 0; cp < 2; cp++) {
                float a_i[2], a_f[2], a_o[2], a_g[2];
                float x_i[2], x_f[2], x_o[2], x_g[2];
                unpack2(acc2[0 + j][r][cp], a_i[0], a_i[1]);
                unpack2(acc2[2 + j][r][cp], a_f[0], a_f[1]);
                unpack2(acc2[4 + j][r][cp], a_o[0], a_o[1]);
                unpack2(acc2[6 + j][r][cp], a_g[0], a_g[1]);
                unpack2(blob[((((0 + j) * 2 + r) * 2 + cp) << 8) + tid], x_i[0], x_i[1]);
                unpack2(blob[((((2 + j) * 2 + r) * 2 + cp) << 8) + tid], x_f[0], x_f[1]);
                unpack2(blob[((((4 + j) * 2 + r) * 2 + cp) << 8) + tid], x_o[0], x_o[1]);
                unpack2(blob[((((6 + j) * 2 + r) * 2 + cp) << 8) + tid], x_g[0], x_g[1]);
                #pragma unroll
                for (int u = 0; u < 2; u++) {
                    const int xx = tileX + 4 * cq + cp * 2 + u;
                    const size_t idx = ((size_t)b * C + ch) * (size_t)(H * W)
                                     + (size_t)y * W + xx;
                    const float gi = a_i[u] + x_i[u] + bi;
                    const float gf = a_f[u] + x_f[u] + bf;
                    const float go = a_o[u] + x_o[u] + bo;
                    const float gg = a_g[u] + x_g[u] + bg;
                    const float si = 1.0f / (1.0f + __expf(-gi));
                    const float sf = 1.0f / (1.0f + __expf(-gf));
                    const float so = 1.0f / (1.0f + __expf(-go));
                    const float tg = tanhf(gg);
                    const float cn = sf * c[idx] + si * tg;
                    c[idx] = cn;
                    h_out[idx] = so * tanhf(cn);
                }
            }
        }
    }
}

__global__ void avg_kernel(const float* __restrict__ a, const float* __restrict__ b,
                           float* __restrict__ out, size_t n)
{
    size_t i = (size_t)blockIdx.x * blockDim.x + threadIdx.x;
    if (i < n) out[i] = 0.5f * (a[i] + b[i]);
}

// ---------------------------------------------------------------------------
// Launch
// ---------------------------------------------------------------------------
extern "C" void kernel_launch(void* const* d_in, const int* in_sizes, int n_in,
                              void* d_out, int out_size)
{
    const float* feat0 = (const float*)d_in[0];
    const float* feat1 = (const float*)d_in[1];
    const int*   mask  = (const int*)  d_in[2];
    const float* Wf0   = (const float*)d_in[3];
    const float* bf0   = (const float*)d_in[4];
    const float* Wb0   = (const float*)d_in[5];
    const float* bb0   = (const float*)d_in[6];
    const float* Wf1   = (const float*)d_in[7];
    const float* bf1   = (const float*)d_in[8];
    const float* Wb1   = (const float*)d_in[9];
    const float* bb1   = (const float*)d_in[10];
    float* out = (float*)d_out;

    float* buf = nullptr;
    cudaGetSymbolAddress((void**)&buf, g_buf);
    unsigned long long* xg = nullptr;
    cudaGetSymbolAddress((void**)&xg, g_xg);

    static cudaStream_t strm[3];
    static cudaEvent_t evFork, evJoin[3];
    static bool inited = false;
    if (!inited) {
        for (int i = 0; i < 3; i++)
            cudaStreamCreateWithFlags(&strm[i], cudaStreamNonBlocking);
        cudaEventCreateWithFlags(&evFork, cudaEventDisableTiming);
        for (int i = 0; i < 3; i++)
            cudaEventCreateWithFlags(&evJoin[i], cudaEventDisableTiming);
        cudaFuncSetAttribute(conv_x_pre<64, 64, 64>,
            cudaFuncAttributeMaxDynamicSharedMemorySize, SMEM_BYTES);
        cudaFuncSetAttribute(conv_x_pre<128, 32, 32>,
            cudaFuncAttributeMaxDynamicSharedMemorySize, SMEM_BYTES);
        cudaFuncSetAttribute(convlstm_step<64, 64, 64>,
            cudaFuncAttributeMaxDynamicSharedMemorySize, SMEM_BYTES);
        cudaFuncSetAttribute(convlstm_step<128, 32, 32>,
            cudaFuncAttributeMaxDynamicSharedMemorySize, SMEM_BYTES);
        inited = true;
    }

    zero_kernel<<<(unsigned)((STATE_TOTAL + 255) / 256), 256>>>(buf, STATE_TOTAL);
    transpose_all<<<11520, 256>>>(Wf0, Wb0, Wf1, Wb1,
                                  buf + OFF_WTF0, buf + OFF_WTB0,
                                  buf + OFF_WTF1, buf + OFF_WTB1);
    cudaEventRecord(evFork, 0);
    for (int i = 0; i < 3; i++) cudaStreamWaitEvent(strm[i], evFork, 0);

    const int T = 16, B = 8;
    const dim3 gridPre0(16, 4, T * B);
    const dim3 gridPre1(4, 8, T * B);
    const dim3 grid0(16, 4, B);
    const dim3 grid1(4, 8, B);

    const float* WTs[4] = { buf + OFF_WTF0, buf + OFF_WTB0, buf + OFF_WTF1, buf + OFF_WTB1 };
    unsigned long long* XGs[4] = { xg + XG_F0, xg + XG_B0, xg + XG_F1, xg + XG_B1 };

    // phase 1: one big precompute launch per cell
    conv_x_pre<64, 64, 64><<<gridPre0, 256, SMEM_BYTES>>>(feat0, WTs[0], XGs[0], mask);
    conv_x_pre<64, 64, 64><<<gridPre0, 256, SMEM_BYTES, strm[0]>>>(feat0, WTs[1], XGs[1], mask);
    conv_x_pre<128, 32, 32><<<gridPre1, 256, SMEM_BYTES, strm[1]>>>(feat1, WTs[2], XGs[2], mask);
    conv_x_pre<128, 32, 32><<<gridPre1, 256, SMEM_BYTES, strm[2]>>>(feat1, WTs[3], XGs[3], mask);

    float* hf0[2] = { buf + OFF_HF0A, buf + OFF_HF0B };
    float* hb0[2] = { buf + OFF_HB0A, buf + OFF_HB0B };
    float* hf1[2] = { buf + OFF_HF1A, buf + OFF_HF1B };
    float* hb1[2] = { buf + OFF_HB1A, buf + OFF_HB1B };

    // phase 2: recurrent chains
    for (int t = 0; t < T; ++t) {
        const int p = t & 1, q = p ^ 1;
        convlstm_step<64, 64, 64><<<grid0, 256, SMEM_BYTES>>>(
            hf0[p], hf0[q], buf + OFF_CF0, WTs[0], bf0, XGs[0], mask + t * B, t);
    }
    for (int t = 0; t < T; ++t) {
        const int p = t & 1, q = p ^ 1;
        convlstm_step<64, 64, 64><<<grid0, 256, SMEM_BYTES, strm[0]>>>(
            hb0[p], hb0[q], buf + OFF_CB0, WTs[1], bb0, XGs[1], mask + t * B, t);
    }
    for (int t = 0; t < T; ++t) {
        const int p = t & 1, q = p ^ 1;
        convlstm_step<128, 32, 32><<<grid1, 256, SMEM_BYTES, strm[1]>>>(
            hf1[p], hf1[q], buf + OFF_CF1, WTs[2], bf1, XGs[2], mask + t * B, t);
    }
    for (int t = 0; t < T; ++t) {
        const int p = t & 1, q = p ^ 1;
        convlstm_step<128, 32, 32><<<grid1, 256, SMEM_BYTES, strm[2]>>>(
            hb1[p], hb1[q], buf + OFF_CB1, WTs[3], bb1, XGs[3], mask + t * B, t);
    }

    for (int i = 0; i < 3; i++) {
        cudaEventRecord(evJoin[i], strm[i]);
        cudaStreamWaitEvent(0, evJoin[i], 0);
    }

    avg_kernel<<<(unsigned)((ST0 + 255) / 256), 256>>>(hf0[0], hb0[0], out, ST0);
    avg_kernel<<<(unsigned)((ST1 + 255) / 256), 256>>>(hf1[0], hb1[0], out + ST0, ST1);
}

// round 13
// speedup vs baseline: 2.0069x; 2.0069x over previous
#include <cuda_runtime.h>
#include <cuda_bf16.h>
#include <cstdint>
#include <math.h>

#define ST0 2097152ull
#define ST1 1048576ull
#define WT0_SZ (2ull * 72 * 64 * 64)
#define WT1_SZ (2ull * 72 * 128 * 128)

#define OFF_HF0A 0ull
#define OFF_HF0B (OFF_HF0A + ST0)
#define OFF_CF0  (OFF_HF0B + ST0)
#define OFF_HB0A (OFF_CF0  + ST0)
#define OFF_HB0B (OFF_HB0A + ST0)
#define OFF_CB0  (OFF_HB0B + ST0)
#define OFF_HF1A (OFF_CB0  + ST0)
#define OFF_HF1B (OFF_HF1A + ST1)
#define OFF_CF1  (OFF_HF1B + ST1)
#define OFF_HB1A (OFF_CF1  + ST1)
#define OFF_HB1B (OFF_HB1A + ST1)
#define OFF_CB1  (OFF_HB1B + ST1)
#define OFF_WTF0 (OFF_CB1  + ST1)
#define OFF_WTB0 (OFF_WTF0 + WT0_SZ)
#define OFF_WTF1 (OFF_WTB0 + WT0_SZ)
#define OFF_WTB1 (OFF_WTF1 + WT1_SZ)
#define BUF_TOTAL (OFF_WTB1 + WT1_SZ)

__device__ float g_buf[BUF_TOTAL];
#define STATE_TOTAL (OFF_WTF0)

// fp32 x-gate blobs, fragment layout: 16384 floats per CTA
#define XG0_CELL 134217728ull   // 128z*4g*16tile*16384
#define XG1_CELL 67108864ull    // 128z*8g*4tile*16384
#define XG_F0 0ull
#define XG_B0 (XG_F0 + XG0_CELL)
#define XG_F1 (XG_B0 + XG0_CELL)
#define XG_B1 (XG_F1 + XG1_CELL)
#define XG_TOTAL (XG_B1 + XG1_CELL)
__device__ float g_xg[XG_TOTAL];

__global__ void zero_kernel(float* __restrict__ p, size_t n) {
    size_t i = (size_t)blockIdx.x * blockDim.x + threadIdx.x;
    if (i < n) p[i] = 0.0f;
}

// ---------------------------------------------------------------------------
// Split each weight into (hi,lo) bf16, MMA layout:
//   e = ((coGrp*CB2 + ciblk)*64 + o)*144 + tap*16 + ciL
//   W row = (o>>4)*C + coGrp*16 + (o&15); ci = ciblk*16 + ciL
// hi at O[e], lo at O[N+e].
// ---------------------------------------------------------------------------
__global__ void split_weights(const float* __restrict__ W0f, const float* __restrict__ W0b,
                              const float* __restrict__ W1f, const float* __restrict__ W1b,
                              __nv_bfloat16* __restrict__ o0f, __nv_bfloat16* __restrict__ o0b,
                              __nv_bfloat16* __restrict__ o1f, __nv_bfloat16* __restrict__ o1b)
{
    const int N0 = 294912, N1 = 1179648;
    long long j = (long long)blockIdx.x * 256 + threadIdx.x;
    const float* Wsrc; __nv_bfloat16* O; int C, N;
    if (j < N0)              { Wsrc = W0f; O = o0f; C = 64;  N = N0; }
    else if ((j -= N0) < N0) { Wsrc = W0b; O = o0b; C = 64;  N = N0; }
    else if ((j -= N0) < N1) { Wsrc = W1f; O = o1f; C = 128; N = N1; }
    else if ((j -= N1) < N1) { Wsrc = W1b; O = o1b; C = 128; N = N1; }
    else return;
    int e = (int)j;
    int k = e % 144;
    int o = (e / 144) % 64;
    int CB2 = (2 * C) / 16;
    int cib = (e / 9216) % CB2;
    int coGrp = e / (9216 * CB2);
    int tap = k >> 4, ciL = k & 15;
    int ci = cib * 16 + ciL;
    int row = (o >> 4) * C + coGrp * 16 + (o & 15);
    float w = Wsrc[((size_t)row * (2 * C) + ci) * 9 + tap];
    __nv_bfloat16 hi = __float2bfloat16(w);
    O[e] = hi;
    O[N + e] = __float2bfloat16(w - __bfloat162float(hi));
}

__device__ __forceinline__ void cpa16(unsigned dst, const void* src) {
    asm volatile("cp.async.cg.shared.global [%0], [%1], 16;" :: "r"(dst), "l"(src));
}
__device__ __forceinline__ void cpa16z(unsigned dst, const void* src, bool v) {
    int sz = v ? 16 : 0;
    asm volatile("cp.async.cg.shared.global [%0], [%1], 16, %2;"
                 :: "r"(dst), "l"(src), "r"(sz));
}
__device__ __forceinline__ void cpa_commit() {
    asm volatile("cp.async.commit_group;" ::: "memory");
}
__device__ __forceinline__ void mma16816(float (&d)[4], const unsigned (&a)[4],
                                         unsigned b0, unsigned b1) {
    asm volatile(
        "mma.sync.aligned.m16n8k16.row.col.f32.bf16.bf16.f32 "
        "{%0,%1,%2,%3},{%4,%5,%6,%7},{%8,%9},{%0,%1,%2,%3};"
        : "+f"(d[0]), "+f"(d[1]), "+f"(d[2]), "+f"(d[3])
        : "r"(a[0]), "r"(a[1]), "r"(a[2]), "r"(a[3]), "r"(b0), "r"(b1));
}

#define TSP 16
#define RAW_CI 436                       // padded ci stride (floats)
#define RAW_BUF (16 * RAW_CI)            // 6976 floats / buffer
#define P_OFF (2 * RAW_BUF * 4)          // 55808 B
#define P_ELEMS (18 * 24 * 18)           // pixel-stride 18 bf16
#define A_OFF (P_OFF + 2 * P_ELEMS * 2)  // 86912 B
#define A_ROW 152                        // padded row stride (bf16)
#define A_BUF_B (64 * A_ROW * 2)         // 19456 B per (dbuf,half)
#define SMEM_BYTES (A_OFF + 4 * A_BUF_B) // 164736 B

// ---------------------------------------------------------------------------
// MMA conv core: 64 outputs x 256 px over ci-blocks [ciblkBase, +C/16).
// ---------------------------------------------------------------------------
template<int C, int H, int W>
__device__ __forceinline__ void conv_mma(
    const float* __restrict__ base, const __nv_bfloat16* __restrict__ Acell,
    int Ncell, int ciblkBase, int coGrp, int tileY, int tileX,
    float (&Cacc)[4][4][4])
{
    extern __shared__ char dsm[];
    float* raw = (float*)dsm;
    __nv_bfloat16* Phi = (__nv_bfloat16*)(dsm + P_OFF);
    __nv_bfloat16* Plo = Phi + P_ELEMS;
    char* Ab = dsm + A_OFF;
    const unsigned sRaw = (unsigned)__cvta_generic_to_shared(raw);
    const unsigned sA   = (unsigned)__cvta_generic_to_shared(Ab);

    const int tid = threadIdx.x;
    const int wid = tid >> 5, lane = tid & 31;
    const int g = lane >> 2, tig = lane & 3;
    const int CB2 = (2 * C) / 16, NBLK = C / 16;

    auto stage = [&](int blk, int dbuf) {
        for (int i = tid; i < 16 * 108; i += 256) {
            const int ci = i / 108, rem = i - ci * 108;
            const int r = rem / 6, k = rem - r * 6;
            const float* srcp = base + (size_t)(blk * 16 + ci) * H * W;
            const int gy = tileY - 1 + r;
            const bool vr = (gy >= 0 && gy < H);
            const bool vc = (k == 0) ? (tileX > 0) : ((k < 5) ? true : (tileX + 16 < W));
            const bool v = vr && vc;
            const float* sp = srcp + (v ? (gy * W + tileX - 4 + 4 * k) : 0);
            cpa16z(sRaw + (unsigned)(dbuf * RAW_BUF * 4 + ci * (RAW_CI * 4)
                                     + r * 96 + k * 16), sp, v);
        }
        const size_t eb = ((size_t)coGrp * CB2 + (size_t)(ciblkBase + blk)) * 9216;
        for (int i = tid; i < 2 * 1152; i += 256) {
            const int half = i / 1152, j = i - half * 1152;
            const int row = j / 18, ch = j - row * 18;
            const __nv_bfloat16* src = Acell + (half ? Ncell : 0) + eb + row * 144 + ch * 8;
            cpa16(sA + (unsigned)((dbuf * 2 + half) * A_BUF_B + row * (A_ROW * 2)
                                  + ch * 16), src);
        }
        cpa_commit();
    };

    stage(0, 0);
    for (int blk = 0; blk < NBLK; ++blk) {
        const int cur = blk & 1;
        __syncthreads();                       // prev compute done everywhere
        if (blk + 1 < NBLK) {
            stage(blk + 1, cur ^ 1);
            asm volatile("cp.async.wait_group 1;" ::: "memory");
        } else {
            asm volatile("cp.async.wait_group 0;" ::: "memory");
        }
        __syncthreads();                       // raw+A(cur) visible

        const float* rb = raw + cur * RAW_BUF;
        for (int i = tid; i < 3456; i += 256) {
            const int r = i / 192, rem = i - r * 192;
            const int cc = rem >> 3, cp = rem & 7;
            const float v0 = rb[(2 * cp) * RAW_CI + r * 24 + cc];
            const float v1 = rb[(2 * cp + 1) * RAW_CI + r * 24 + cc];
            __nv_bfloat162 h2 = __floats2bfloat162_rn(v0, v1);
            const float l0 = v0 - __low2float(h2);
            const float l1 = v1 - __high2float(h2);
            __nv_bfloat162 l2 = __floats2bfloat162_rn(l0, l1);
            const int pi = (r * 24 + cc) * 18 + 2 * cp;
            *(unsigned*)&Phi[pi] = *(unsigned*)&h2;
            *(unsigned*)&Plo[pi] = *(unsigned*)&l2;
        }
        __syncthreads();                       // P ready

        const __nv_bfloat16* Ah = (const __nv_bfloat16*)(Ab + (cur * 2 + 0) * A_BUF_B);
        const __nv_bfloat16* Al = (const __nv_bfloat16*)(Ab + (cur * 2 + 1) * A_BUF_B);
        #pragma unroll
        for (int tap = 0; tap < 9; ++tap) {
            const int dy = tap / 3, dx = tap - dy * 3;
            const int kb = tap * 16 + 2 * tig;
            unsigned ah[4][4], al[4][4];
            #pragma unroll
            for (int m = 0; m < 4; ++m) {
                const int o = m * 16 + g;
                ah[m][0] = *(const unsigned*)&Ah[o * A_ROW + kb];
                ah[m][1] = *(const unsigned*)&Ah[(o + 8) * A_ROW + kb];
                ah[m][2] = *(const unsigned*)&Ah[o * A_ROW + kb + 8];
                ah[m][3] = *(const unsigned*)&Ah[(o + 8) * A_ROW + kb + 8];
                al[m][0] = *(const unsigned*)&Al[o * A_ROW + kb];
                al[m][1] = *(const unsigned*)&Al[(o + 8) * A_ROW + kb];
                al[m][2] = *(const unsigned*)&Al[o * A_ROW + kb + 8];
                al[m][3] = *(const unsigned*)&Al[(o + 8) * A_ROW + kb + 8];
            }
            #pragma unroll
            for (int n = 0; n < 4; ++n) {
                const int r = 2 * wid + (n >> 1) + dy;
                const int cc = (n & 1) * 8 + g + dx + 3;
                const int pb = (r * 24 + cc) * 18 + 2 * tig;
                const unsigned bh0 = *(const unsigned*)&Phi[pb];
                const unsigned bh1 = *(const unsigned*)&Phi[pb + 8];
                const unsigned bl0 = *(const unsigned*)&Plo[pb];
                const unsigned bl1 = *(const unsigned*)&Plo[pb + 8];
                #pragma unroll
                for (int m = 0; m < 4; ++m) {
                    mma16816(Cacc[m][n], ah[m], bh0, bh1);
                    mma16816(Cacc[m][n], ah[m], bl0, bl1);
                    mma16816(Cacc[m][n], al[m], bh0, bh1);
                }
            }
        }
    }
    __syncthreads();
}

template<int C, int H, int W>
__global__ __launch_bounds__(256, 1)
void conv_x_pre(const float* __restrict__ feat, const __nv_bfloat16* __restrict__ Acell,
                int Ncell, float* __restrict__ xg, const int* __restrict__ mask)
{
    const int z = blockIdx.z;
    if (mask[z] <= 0) return;
    const int coGrp = blockIdx.y;
    const int tilesX = W / TSP, nTiles = (H / TSP) * tilesX;
    const int tileY = (blockIdx.x / tilesX) * TSP;
    const int tileX = (blockIdx.x % tilesX) * TSP;

    float Cacc[4][4][4];
    #pragma unroll
    for (int m = 0; m < 4; m++)
        #pragma unroll
        for (int n = 0; n < 4; n++)
            #pragma unroll
            for (int r = 0; r < 4; r++) Cacc[m][n][r] = 0.0f;

    conv_mma<C, H, W>(feat + (size_t)z * C * H * W, Acell, Ncell, 0, coGrp,
                      tileY, tileX, Cacc);

    float* blob = xg + (((size_t)z * (C / 16) + coGrp) * nTiles + blockIdx.x) * 16384;
    #pragma unroll
    for (int m = 0; m < 4; m++)
        #pragma unroll
        for (int n = 0; n < 4; n++)
            #pragma unroll
            for (int r = 0; r < 4; r++)
                blob[(((m * 4 + n) * 4 + r) << 8) + threadIdx.x] = Cacc[m][n][r];
}

template<int C, int H, int W>
__global__ __launch_bounds__(256, 1)
void convlstm_step(const float* __restrict__ h_in, float* __restrict__ h_out,
                   float* __restrict__ c, const __nv_bfloat16* __restrict__ Acell,
                   int Ncell, const float* __restrict__ bias,
                   const float* __restrict__ xg, const int* __restrict__ mask_t, int t)
{
    const int b = blockIdx.z;
    const int coGrp = blockIdx.y, coBase = coGrp * 16;
    const int tilesX = W / TSP, nTiles = (H / TSP) * tilesX;
    const int tileY = (blockIdx.x / tilesX) * TSP;
    const int tileX = (blockIdx.x % tilesX) * TSP;
    const int tid = threadIdx.x;

    if (mask_t[b] <= 0) {
        for (int i = tid; i < 16 * TSP * TSP; i += 256) {
            const int chL = i >> 8, rem = i & 255;
            const size_t idx = ((size_t)b * C + coBase + chL) * (size_t)(H * W)
                             + (size_t)(tileY + (rem >> 4)) * W + tileX + (rem & 15);
            h_out[idx] = h_in[idx];
        }
        return;
    }

    const int wid = tid >> 5, lane = tid & 31;
    const int g = lane >> 2, tig = lane & 3;

    float Cacc[4][4][4];
    #pragma unroll
    for (int m = 0; m < 4; m++)
        #pragma unroll
        for (int n = 0; n < 4; n++)
            #pragma unroll
            for (int r = 0; r < 4; r++) Cacc[m][n][r] = 0.0f;

    conv_mma<C, H, W>(h_in + (size_t)b * C * H * W, Acell, Ncell, C / 16, coGrp,
                      tileY, tileX, Cacc);

    const float* blob = xg +
        (((size_t)(t * 8 + b) * (C / 16) + coGrp) * nTiles + blockIdx.x) * 16384;

    #pragma unroll
    for (int hc = 0; hc < 2; hc++) {
        const int chG = coBase + g + hc * 8;
        const float bi = bias[0 * C + chG];
        const float bf = bias[1 * C + chG];
        const float bo = bias[2 * C + chG];
        const float bg = bias[3 * C + chG];
        #pragma unroll
        for (int n = 0; n < 4; n++) {
            const int py = 2 * wid + (n >> 1);
            #pragma unroll
            for (int u = 0; u < 2; u++) {
                const int r = hc * 2 + u;
                const int xx = (n & 1) * 8 + 2 * tig + u;
                const float gi = Cacc[0][n][r] + blob[(((0 * 4 + n) * 4 + r) << 8) + tid] + bi;
                const float gf = Cacc[1][n][r] + blob[(((1 * 4 + n) * 4 + r) << 8) + tid] + bf;
                const float go = Cacc[2][n][r] + blob[(((2 * 4 + n) * 4 + r) << 8) + tid] + bo;
                const float gg = Cacc[3][n][r] + blob[(((3 * 4 + n) * 4 + r) << 8) + tid] + bg;
                const size_t idx = ((size_t)b * C + chG) * (size_t)(H * W)
                                 + (size_t)(tileY + py) * W + tileX + xx;
                const float si = 1.0f / (1.0f + __expf(-gi));
                const float sf = 1.0f / (1.0f + __expf(-gf));
                const float so = 1.0f / (1.0f + __expf(-go));
                const float tg = tanhf(gg);
                const float cn = sf * c[idx] + si * tg;
                c[idx] = cn;
                h_out[idx] = so * tanhf(cn);
            }
        }
    }
}

__global__ void avg_kernel(const float* __restrict__ a, const float* __restrict__ b,
                           float* __restrict__ out, size_t n)
{
    size_t i = (size_t)blockIdx.x * blockDim.x + threadIdx.x;
    if (i < n) out[i] = 0.5f * (a[i] + b[i]);
}

extern "C" void kernel_launch(void* const* d_in, const int* in_sizes, int n_in,
                              void* d_out, int out_size)
{
    const float* feat0 = (const float*)d_in[0];
    const float* feat1 = (const float*)d_in[1];
    const int*   mask  = (const int*)  d_in[2];
    const float* Wf0   = (const float*)d_in[3];
    const float* bf0   = (const float*)d_in[4];
    const float* Wb0   = (const float*)d_in[5];
    const float* bb0   = (const float*)d_in[6];
    const float* Wf1   = (const float*)d_in[7];
    const float* bf1   = (const float*)d_in[8];
    const float* Wb1   = (const float*)d_in[9];
    const float* bb1   = (const float*)d_in[10];
    float* out = (float*)d_out;

    float* buf = nullptr;
    cudaGetSymbolAddress((void**)&buf, g_buf);
    float* xg = nullptr;
    cudaGetSymbolAddress((void**)&xg, g_xg);

    static cudaStream_t strm[3];
    static cudaEvent_t evFork, evJoin[3];
    static bool inited = false;
    if (!inited) {
        for (int i = 0; i < 3; i++)
            cudaStreamCreateWithFlags(&strm[i], cudaStreamNonBlocking);
        cudaEventCreateWithFlags(&evFork, cudaEventDisableTiming);
        for (int i = 0; i < 3; i++)
            cudaEventCreateWithFlags(&evJoin[i], cudaEventDisableTiming);
        cudaFuncSetAttribute(conv_x_pre<64, 64, 64>,
            cudaFuncAttributeMaxDynamicSharedMemorySize, SMEM_BYTES);
        cudaFuncSetAttribute(conv_x_pre<128, 32, 32>,
            cudaFuncAttributeMaxDynamicSharedMemorySize, SMEM_BYTES);
        cudaFuncSetAttribute(convlstm_step<64, 64, 64>,
            cudaFuncAttributeMaxDynamicSharedMemorySize, SMEM_BYTES);
        cudaFuncSetAttribute(convlstm_step<128, 32, 32>,
            cudaFuncAttributeMaxDynamicSharedMemorySize, SMEM_BYTES);
        inited = true;
    }

    __nv_bfloat16* A0f = (__nv_bfloat16*)(buf + OFF_WTF0);
    __nv_bfloat16* A0b = (__nv_bfloat16*)(buf + OFF_WTB0);
    __nv_bfloat16* A1f = (__nv_bfloat16*)(buf + OFF_WTF1);
    __nv_bfloat16* A1b = (__nv_bfloat16*)(buf + OFF_WTB1);
    const int N0 = 294912, N1 = 1179648;

    zero_kernel<<<(unsigned)((STATE_TOTAL + 255) / 256), 256>>>(buf, STATE_TOTAL);
    split_weights<<<11520, 256>>>(Wf0, Wb0, Wf1, Wb1, A0f, A0b, A1f, A1b);
    cudaEventRecord(evFork, 0);
    for (int i = 0; i < 3; i++) cudaStreamWaitEvent(strm[i], evFork, 0);

    const int T = 16, B = 8;
    const dim3 gridPre0(16, 4, T * B);
    const dim3 gridPre1(4, 8, T * B);
    const dim3 grid0(16, 4, B);
    const dim3 grid1(4, 8, B);

    conv_x_pre<64, 64, 64><<<gridPre0, 256, SMEM_BYTES>>>(
        feat0, A0f, N0, xg + XG_F0, mask);
    conv_x_pre<64, 64, 64><<<gridPre0, 256, SMEM_BYTES, strm[0]>>>(
        feat0, A0b, N0, xg + XG_B0, mask);
    conv_x_pre<128, 32, 32><<<gridPre1, 256, SMEM_BYTES, strm[1]>>>(
        feat1, A1f, N1, xg + XG_F1, mask);
    conv_x_pre<128, 32, 32><<<gridPre1, 256, SMEM_BYTES, strm[2]>>>(
        feat1, A1b, N1, xg + XG_B1, mask);

    float* hf0[2] = { buf + OFF_HF0A, buf + OFF_HF0B };
    float* hb0[2] = { buf + OFF_HB0A, buf + OFF_HB0B };
    float* hf1[2] = { buf + OFF_HF1A, buf + OFF_HF1B };
    float* hb1[2] = { buf + OFF_HB1A, buf + OFF_HB1B };

    for (int t = 0; t < T; ++t) {
        const int p = t & 1, q = p ^ 1;
        convlstm_step<64, 64, 64><<<grid0, 256, SMEM_BYTES>>>(
            hf0[p], hf0[q], buf + OFF_CF0, A0f, N0, bf0, xg + XG_F0, mask + t * B, t);
    }
    for (int t = 0; t < T; ++t) {
        const int p = t & 1, q = p ^ 1;
        convlstm_step<64, 64, 64><<<grid0, 256, SMEM_BYTES, strm[0]>>>(
            hb0[p], hb0[q], buf + OFF_CB0, A0b, N0, bb0, xg + XG_B0, mask + t * B, t);
    }
    for (int t = 0; t < T; ++t) {
        const int p = t & 1, q = p ^ 1;
        convlstm_step<128, 32, 32><<<grid1, 256, SMEM_BYTES, strm[1]>>>(
            hf1[p], hf1[q], buf + OFF_CF1, A1f, N1, bf1, xg + XG_F1, mask + t * B, t);
    }
    for (int t = 0; t < T; ++t) {
        const int p = t & 1, q = p ^ 1;
        convlstm_step<128, 32, 32><<<grid1, 256, SMEM_BYTES, strm[2]>>>(
            hb1[p], hb1[q], buf + OFF_CB1, A1b, N1, bb1, xg + XG_B1, mask + t * B, t);
    }

    for (int i = 0; i < 3; i++) {
        cudaEventRecord(evJoin[i], strm[i]);
        cudaStreamWaitEvent(0, evJoin[i], 0);
    }

    avg_kernel<<<(unsigned)((ST0 + 255) / 256), 256>>>(hf0[0], hb0[0], out, ST0);
    avg_kernel<<<(unsigned)((ST1 + 255) / 256), 256>>>(hf1[0], hb1[0], out + ST0, ST1);
}

// round 14
// speedup vs baseline: 2.7266x; 1.3586x over previous
#include <cuda_runtime.h>
#include <cuda_bf16.h>
#include <cstdint>
#include <math.h>

#define ST0 2097152ull
#define ST1 1048576ull
#define WT0_SZ (2ull * 72 * 64 * 64)
#define WT1_SZ (2ull * 72 * 128 * 128)

#define OFF_HF0A 0ull
#define OFF_HF0B (OFF_HF0A + ST0)
#define OFF_CF0  (OFF_HF0B + ST0)
#define OFF_HB0A (OFF_CF0  + ST0)
#define OFF_HB0B (OFF_HB0A + ST0)
#define OFF_CB0  (OFF_HB0B + ST0)
#define OFF_HF1A (OFF_CB0  + ST0)
#define OFF_HF1B (OFF_HF1A + ST1)
#define OFF_CF1  (OFF_HF1B + ST1)
#define OFF_HB1A (OFF_CF1  + ST1)
#define OFF_HB1B (OFF_HB1A + ST1)
#define OFF_CB1  (OFF_HB1B + ST1)
#define OFF_WTF0 (OFF_CB1  + ST1)
#define OFF_WTB0 (OFF_WTF0 + WT0_SZ)
#define OFF_WTF1 (OFF_WTB0 + WT0_SZ)
#define OFF_WTB1 (OFF_WTF1 + WT1_SZ)
#define BUF_TOTAL (OFF_WTB1 + WT1_SZ)

__device__ float g_buf[BUF_TOTAL];
#define STATE_TOTAL (OFF_WTF0)

#define XG0_CELL 134217728ull
#define XG1_CELL 67108864ull
#define XG_F0 0ull
#define XG_B0 (XG_F0 + XG0_CELL)
#define XG_F1 (XG_B0 + XG0_CELL)
#define XG_B1 (XG_F1 + XG1_CELL)
#define XG_TOTAL (XG_B1 + XG1_CELL)
__device__ float g_xg[XG_TOTAL];

__global__ void zero_kernel(float* __restrict__ p, size_t n) {
    size_t i = (size_t)blockIdx.x * blockDim.x + threadIdx.x;
    if (i < n) p[i] = 0.0f;
}

// Split each weight into (hi,lo) bf16, MMA layout (identical to round 13).
__global__ void split_weights(const float* __restrict__ W0f, const float* __restrict__ W0b,
                              const float* __restrict__ W1f, const float* __restrict__ W1b,
                              __nv_bfloat16* __restrict__ o0f, __nv_bfloat16* __restrict__ o0b,
                              __nv_bfloat16* __restrict__ o1f, __nv_bfloat16* __restrict__ o1b)
{
    const int N0 = 294912, N1 = 1179648;
    long long j = (long long)blockIdx.x * 256 + threadIdx.x;
    const float* Wsrc; __nv_bfloat16* O; int C, N;
    if (j < N0)              { Wsrc = W0f; O = o0f; C = 64;  N = N0; }
    else if ((j -= N0) < N0) { Wsrc = W0b; O = o0b; C = 64;  N = N0; }
    else if ((j -= N0) < N1) { Wsrc = W1f; O = o1f; C = 128; N = N1; }
    else if ((j -= N1) < N1) { Wsrc = W1b; O = o1b; C = 128; N = N1; }
    else return;
    int e = (int)j;
    int k = e % 144;
    int o = (e / 144) % 64;
    int CB2 = (2 * C) / 16;
    int cib = (e / 9216) % CB2;
    int coGrp = e / (9216 * CB2);
    int tap = k >> 4, ciL = k & 15;
    int ci = cib * 16 + ciL;
    int row = (o >> 4) * C + coGrp * 16 + (o & 15);
    float w = Wsrc[((size_t)row * (2 * C) + ci) * 9 + tap];
    __nv_bfloat16 hi = __float2bfloat16(w);
    O[e] = hi;
    O[N + e] = __float2bfloat16(w - __bfloat162float(hi));
}

__device__ __forceinline__ void cpa16(unsigned dst, const void* src) {
    asm volatile("cp.async.cg.shared.global [%0], [%1], 16;" :: "r"(dst), "l"(src));
}
__device__ __forceinline__ void cpa16z(unsigned dst, const void* src, bool v) {
    int sz = v ? 16 : 0;
    asm volatile("cp.async.cg.shared.global [%0], [%1], 16, %2;"
                 :: "r"(dst), "l"(src), "r"(sz));
}
__device__ __forceinline__ void cpa_commit() {
    asm volatile("cp.async.commit_group;" ::: "memory");
}
__device__ __forceinline__ void mma16816(float (&d)[4], const unsigned (&a)[4],
                                         unsigned b0, unsigned b1) {
    asm volatile(
        "mma.sync.aligned.m16n8k16.row.col.f32.bf16.bf16.f32 "
        "{%0,%1,%2,%3},{%4,%5,%6,%7},{%8,%9},{%0,%1,%2,%3};"
        : "+f"(d[0]), "+f"(d[1]), "+f"(d[2]), "+f"(d[3])
        : "r"(a[0]), "r"(a[1]), "r"(a[2]), "r"(a[3]), "r"(b0), "r"(b1));
}

#define TSP 16
#define RAW_CI 436
#define RAW_BUF (16 * RAW_CI)                // 6976 floats, single buffer
#define P_OFF (RAW_BUF * 4)                  // 27904 B
#define P_ELEMS (18 * 24 * 18)
#define A_OFF (P_OFF + 2 * P_ELEMS * 2)      // 59008 B
#define A_ROW 152
#define A_BUF_B (64 * A_ROW * 2)             // 19456 B per half
#define SMEM_BYTES (A_OFF + 2 * A_BUF_B)     // 97920 B -> 2 CTAs/SM

// ---------------------------------------------------------------------------
// MMA conv core, single-buffered smem (occupancy-2 variant).
// ---------------------------------------------------------------------------
template<int C, int H, int W>
__device__ __forceinline__ void conv_mma(
    const float* __restrict__ base, const __nv_bfloat16* __restrict__ Acell,
    int Ncell, int ciblkBase, int coGrp, int tileY, int tileX,
    float (&Cacc)[4][4][4])
{
    extern __shared__ char dsm[];
    float* raw = (float*)dsm;
    __nv_bfloat16* Phi = (__nv_bfloat16*)(dsm + P_OFF);
    __nv_bfloat16* Plo = Phi + P_ELEMS;
    char* Ab = dsm + A_OFF;
    const unsigned sRaw = (unsigned)__cvta_generic_to_shared(raw);
    const unsigned sA   = (unsigned)__cvta_generic_to_shared(Ab);

    const int tid = threadIdx.x;
    const int wid = tid >> 5, lane = tid & 31;
    const int g = lane >> 2, tig = lane & 3;
    const int CB2 = (2 * C) / 16, NBLK = C / 16;

    for (int blk = 0; blk < NBLK; ++blk) {
        __syncthreads();                       // prev MMA done (P/A reusable)
        // stage raw input (fp32) and A weights for this block
        for (int i = tid; i < 16 * 108; i += 256) {
            const int ci = i / 108, rem = i - ci * 108;
            const int r = rem / 6, k = rem - r * 6;
            const float* srcp = base + (size_t)(blk * 16 + ci) * H * W;
            const int gy = tileY - 1 + r;
            const bool vr = (gy >= 0 && gy < H);
            const bool vc = (k == 0) ? (tileX > 0) : ((k < 5) ? true : (tileX + 16 < W));
            const bool v = vr && vc;
            const float* sp = srcp + (v ? (gy * W + tileX - 4 + 4 * k) : 0);
            cpa16z(sRaw + (unsigned)(ci * (RAW_CI * 4) + r * 96 + k * 16), sp, v);
        }
        {
            const size_t eb = ((size_t)coGrp * CB2 + (size_t)(ciblkBase + blk)) * 9216;
            for (int i = tid; i < 2 * 1152; i += 256) {
                const int half = i / 1152, j = i - half * 1152;
                const int row = j / 18, ch = j - row * 18;
                const __nv_bfloat16* src = Acell + (half ? Ncell : 0) + eb
                                         + row * 144 + ch * 8;
                cpa16(sA + (unsigned)(half * A_BUF_B + row * (A_ROW * 2) + ch * 16), src);
            }
        }
        cpa_commit();
        asm volatile("cp.async.wait_group 0;" ::: "memory");
        __syncthreads();                       // staged data visible

        // build split-bf16 patch P
        for (int i = tid; i < 3456; i += 256) {
            const int r = i / 192, rem = i - r * 192;
            const int cc = rem >> 3, cp = rem & 7;
            const float v0 = raw[(2 * cp) * RAW_CI + r * 24 + cc];
            const float v1 = raw[(2 * cp + 1) * RAW_CI + r * 24 + cc];
            __nv_bfloat162 h2 = __floats2bfloat162_rn(v0, v1);
            const float l0 = v0 - __low2float(h2);
            const float l1 = v1 - __high2float(h2);
            __nv_bfloat162 l2 = __floats2bfloat162_rn(l0, l1);
            const int pi = (r * 24 + cc) * 18 + 2 * cp;
            *(unsigned*)&Phi[pi] = *(unsigned*)&h2;
            *(unsigned*)&Plo[pi] = *(unsigned*)&l2;
        }
        __syncthreads();                       // P ready

        const __nv_bfloat16* Ah = (const __nv_bfloat16*)(Ab);
        const __nv_bfloat16* Al = (const __nv_bfloat16*)(Ab + A_BUF_B);
        #pragma unroll
        for (int tap = 0; tap < 9; ++tap) {
            const int dy = tap / 3, dx = tap - dy * 3;
            const int kb = tap * 16 + 2 * tig;
            unsigned ah[4][4], al[4][4];
            #pragma unroll
            for (int m = 0; m < 4; ++m) {
                const int o = m * 16 + g;
                ah[m][0] = *(const unsigned*)&Ah[o * A_ROW + kb];
                ah[m][1] = *(const unsigned*)&Ah[(o + 8) * A_ROW + kb];
                ah[m][2] = *(const unsigned*)&Ah[o * A_ROW + kb + 8];
                ah[m][3] = *(const unsigned*)&Ah[(o + 8) * A_ROW + kb + 8];
                al[m][0] = *(const unsigned*)&Al[o * A_ROW + kb];
                al[m][1] = *(const unsigned*)&Al[(o + 8) * A_ROW + kb];
                al[m][2] = *(const unsigned*)&Al[o * A_ROW + kb + 8];
                al[m][3] = *(const unsigned*)&Al[(o + 8) * A_ROW + kb + 8];
            }
            #pragma unroll
            for (int n = 0; n < 4; ++n) {
                const int r = 2 * wid + (n >> 1) + dy;
                const int cc = (n & 1) * 8 + g + dx + 3;
                const int pb = (r * 24 + cc) * 18 + 2 * tig;
                const unsigned bh0 = *(const unsigned*)&Phi[pb];
                const unsigned bh1 = *(const unsigned*)&Phi[pb + 8];
                const unsigned bl0 = *(const unsigned*)&Plo[pb];
                const unsigned bl1 = *(const unsigned*)&Plo[pb + 8];
                #pragma unroll
                for (int m = 0; m < 4; ++m) {
                    mma16816(Cacc[m][n], ah[m], bh0, bh1);
                    mma16816(Cacc[m][n], ah[m], bl0, bl1);
                    mma16816(Cacc[m][n], al[m], bh0, bh1);
                }
            }
        }
    }
    __syncthreads();
}

template<int C, int H, int W>
__global__ __launch_bounds__(256, 2)
void conv_x_pre(const float* __restrict__ feat, const __nv_bfloat16* __restrict__ Acell,
                int Ncell, float* __restrict__ xg, const int* __restrict__ mask)
{
    const int z = blockIdx.z;
    if (mask[z] <= 0) return;
    const int coGrp = blockIdx.y;
    const int tilesX = W / TSP, nTiles = (H / TSP) * tilesX;
    const int tileY = (blockIdx.x / tilesX) * TSP;
    const int tileX = (blockIdx.x % tilesX) * TSP;

    float Cacc[4][4][4];
    #pragma unroll
    for (int m = 0; m < 4; m++)
        #pragma unroll
        for (int n = 0; n < 4; n++)
            #pragma unroll
            for (int r = 0; r < 4; r++) Cacc[m][n][r] = 0.0f;

    conv_mma<C, H, W>(feat + (size_t)z * C * H * W, Acell, Ncell, 0, coGrp,
                      tileY, tileX, Cacc);

    float* blob = xg + (((size_t)z * (C / 16) + coGrp) * nTiles + blockIdx.x) * 16384;
    #pragma unroll
    for (int m = 0; m < 4; m++)
        #pragma unroll
        for (int n = 0; n < 4; n++)
            #pragma unroll
            for (int r = 0; r < 4; r++)
                blob[(((m * 4 + n) * 4 + r) << 8) + threadIdx.x] = Cacc[m][n][r];
}

template<int C, int H, int W>
__global__ __launch_bounds__(256, 2)
void convlstm_step(const float* __restrict__ h_in, float* __restrict__ h_out,
                   float* __restrict__ c, const __nv_bfloat16* __restrict__ Acell,
                   int Ncell, const float* __restrict__ bias,
                   const float* __restrict__ xg, const int* __restrict__ mask_t, int t)
{
    const int b = blockIdx.z;
    const int coGrp = blockIdx.y, coBase = coGrp * 16;
    const int tilesX = W / TSP, nTiles = (H / TSP) * tilesX;
    const int tileY = (blockIdx.x / tilesX) * TSP;
    const int tileX = (blockIdx.x % tilesX) * TSP;
    const int tid = threadIdx.x;

    if (mask_t[b] <= 0) {
        for (int i = tid; i < 16 * TSP * TSP; i += 256) {
            const int chL = i >> 8, rem = i & 255;
            const size_t idx = ((size_t)b * C + coBase + chL) * (size_t)(H * W)
                             + (size_t)(tileY + (rem >> 4)) * W + tileX + (rem & 15);
            h_out[idx] = h_in[idx];
        }
        return;
    }

    const int wid = tid >> 5, lane = tid & 31;
    const int g = lane >> 2, tig = lane & 3;

    float Cacc[4][4][4];
    #pragma unroll
    for (int m = 0; m < 4; m++)
        #pragma unroll
        for (int n = 0; n < 4; n++)
            #pragma unroll
            for (int r = 0; r < 4; r++) Cacc[m][n][r] = 0.0f;

    conv_mma<C, H, W>(h_in + (size_t)b * C * H * W, Acell, Ncell, C / 16, coGrp,
                      tileY, tileX, Cacc);

    const float* blob = xg +
        (((size_t)(t * 8 + b) * (C / 16) + coGrp) * nTiles + blockIdx.x) * 16384;

    #pragma unroll
    for (int hc = 0; hc < 2; hc++) {
        const int chG = coBase + g + hc * 8;
        const float bi = bias[0 * C + chG];
        const float bf = bias[1 * C + chG];
        const float bo = bias[2 * C + chG];
        const float bg = bias[3 * C + chG];
        #pragma unroll
        for (int n = 0; n < 4; n++) {
            const int py = 2 * wid + (n >> 1);
            #pragma unroll
            for (int u = 0; u < 2; u++) {
                const int r = hc * 2 + u;
                const int xx = (n & 1) * 8 + 2 * tig + u;
                const float gi = Cacc[0][n][r] + blob[(((0 * 4 + n) * 4 + r) << 8) + tid] + bi;
                const float gf = Cacc[1][n][r] + blob[(((1 * 4 + n) * 4 + r) << 8) + tid] + bf;
                const float go = Cacc[2][n][r] + blob[(((2 * 4 + n) * 4 + r) << 8) + tid] + bo;
                const float gg = Cacc[3][n][r] + blob[(((3 * 4 + n) * 4 + r) << 8) + tid] + bg;
                const size_t idx = ((size_t)b * C + chG) * (size_t)(H * W)
                                 + (size_t)(tileY + py) * W + tileX + xx;
                const float si = 1.0f / (1.0f + __expf(-gi));
                const float sf = 1.0f / (1.0f + __expf(-gf));
                const float so = 1.0f / (1.0f + __expf(-go));
                const float tg = tanhf(gg);
                const float cn = sf * c[idx] + si * tg;
                c[idx] = cn;
                h_out[idx] = so * tanhf(cn);
            }
        }
    }
}

__global__ void avg_kernel(const float* __restrict__ a, const float* __restrict__ b,
                           float* __restrict__ out, size_t n)
{
    size_t i = (size_t)blockIdx.x * blockDim.x + threadIdx.x;
    if (i < n) out[i] = 0.5f * (a[i] + b[i]);
}

extern "C" void kernel_launch(void* const* d_in, const int* in_sizes, int n_in,
                              void* d_out, int out_size)
{
    const float* feat0 = (const float*)d_in[0];
    const float* feat1 = (const float*)d_in[1];
    const int*   mask  = (const int*)  d_in[2];
    const float* Wf0   = (const float*)d_in[3];
    const float* bf0   = (const float*)d_in[4];
    const float* Wb0   = (const float*)d_in[5];
    const float* bb0   = (const float*)d_in[6];
    const float* Wf1   = (const float*)d_in[7];
    const float* bf1   = (const float*)d_in[8];
    const float* Wb1   = (const float*)d_in[9];
    const float* bb1   = (const float*)d_in[10];
    float* out = (float*)d_out;

    float* buf = nullptr;
    cudaGetSymbolAddress((void**)&buf, g_buf);
    float* xg = nullptr;
    cudaGetSymbolAddress((void**)&xg, g_xg);

    static cudaStream_t strm[3];
    static cudaEvent_t evFork, evJoin[3];
    static bool inited = false;
    if (!inited) {
        for (int i = 0; i < 3; i++)
            cudaStreamCreateWithFlags(&strm[i], cudaStreamNonBlocking);
        cudaEventCreateWithFlags(&evFork, cudaEventDisableTiming);
        for (int i = 0; i < 3; i++)
            cudaEventCreateWithFlags(&evJoin[i], cudaEventDisableTiming);
        cudaFuncSetAttribute(conv_x_pre<64, 64, 64>,
            cudaFuncAttributeMaxDynamicSharedMemorySize, SMEM_BYTES);
        cudaFuncSetAttribute(conv_x_pre<128, 32, 32>,
            cudaFuncAttributeMaxDynamicSharedMemorySize, SMEM_BYTES);
        cudaFuncSetAttribute(convlstm_step<64, 64, 64>,
            cudaFuncAttributeMaxDynamicSharedMemorySize, SMEM_BYTES);
        cudaFuncSetAttribute(convlstm_step<128, 32, 32>,
            cudaFuncAttributeMaxDynamicSharedMemorySize, SMEM_BYTES);
        inited = true;
    }

    __nv_bfloat16* A0f = (__nv_bfloat16*)(buf + OFF_WTF0);
    __nv_bfloat16* A0b = (__nv_bfloat16*)(buf + OFF_WTB0);
    __nv_bfloat16* A1f = (__nv_bfloat16*)(buf + OFF_WTF1);
    __nv_bfloat16* A1b = (__nv_bfloat16*)(buf + OFF_WTB1);
    const int N0 = 294912, N1 = 1179648;

    zero_kernel<<<(unsigned)((STATE_TOTAL + 255) / 256), 256>>>(buf, STATE_TOTAL);
    split_weights<<<11520, 256>>>(Wf0, Wb0, Wf1, Wb1, A0f, A0b, A1f, A1b);
    cudaEventRecord(evFork, 0);
    for (int i = 0; i < 3; i++) cudaStreamWaitEvent(strm[i], evFork, 0);

    const int T = 16, B = 8;
    const dim3 gridPre0(16, 4, T * B);
    const dim3 gridPre1(4, 8, T * B);
    const dim3 grid0(16, 4, B);
    const dim3 grid1(4, 8, B);

    conv_x_pre<64, 64, 64><<<gridPre0, 256, SMEM_BYTES>>>(
        feat0, A0f, N0, xg + XG_F0, mask);
    conv_x_pre<64, 64, 64><<<gridPre0, 256, SMEM_BYTES, strm[0]>>>(
        feat0, A0b, N0, xg + XG_B0, mask);
    conv_x_pre<128, 32, 32><<<gridPre1, 256, SMEM_BYTES, strm[1]>>>(
        feat1, A1f, N1, xg + XG_F1, mask);
    conv_x_pre<128, 32, 32><<<gridPre1, 256, SMEM_BYTES, strm[2]>>>(
        feat1, A1b, N1, xg + XG_B1, mask);

    float* hf0[2] = { buf + OFF_HF0A, buf + OFF_HF0B };
    float* hb0[2] = { buf + OFF_HB0A, buf + OFF_HB0B };
    float* hf1[2] = { buf + OFF_HF1A, buf + OFF_HF1B };
    float* hb1[2] = { buf + OFF_HB1A, buf + OFF_HB1B };

    for (int t = 0; t < T; ++t) {
        const int p = t & 1, q = p ^ 1;
        convlstm_step<64, 64, 64><<<grid0, 256, SMEM_BYTES>>>(
            hf0[p], hf0[q], buf + OFF_CF0, A0f, N0, bf0, xg + XG_F0, mask + t * B, t);
    }
    for (int t = 0; t < T; ++t) {
        const int p = t & 1, q = p ^ 1;
        convlstm_step<64, 64, 64><<<grid0, 256, SMEM_BYTES, strm[0]>>>(
            hb0[p], hb0[q], buf + OFF_CB0, A0b, N0, bb0, xg + XG_B0, mask + t * B, t);
    }
    for (int t = 0; t < T; ++t) {
        const int p = t & 1, q = p ^ 1;
        convlstm_step<128, 32, 32><<<grid1, 256, SMEM_BYTES, strm[1]>>>(
            hf1[p], hf1[q], buf + OFF_CF1, A1f, N1, bf1, xg + XG_F1, mask + t * B, t);
    }
    for (int t = 0; t < T; ++t) {
        const int p = t & 1, q = p ^ 1;
        convlstm_step<128, 32, 32><<<grid1, 256, SMEM_BYTES, strm[2]>>>(
            hb1[p], hb1[q], buf + OFF_CB1, A1b, N1, bb1, xg + XG_B1, mask + t * B, t);
    }

    for (int i = 0; i < 3; i++) {
        cudaEventRecord(evJoin[i], strm[i]);
        cudaStreamWaitEvent(0, evJoin[i], 0);
    }

    avg_kernel<<<(unsigned)((ST0 + 255) / 256), 256>>>(hf0[0], hb0[0], out, ST0);
    avg_kernel<<<(unsigned)((ST1 + 255) / 256), 256>>>(hf1[0], hb1[0], out + ST0, ST1);
}